// round 4
// baseline (speedup 1.0000x reference)
#include <cuda_runtime.h>
#include <cuda_bf16.h>

// CRF score: -( sum_i logits[i, tags[i]] + sum_{i>0} transitions[tags[i-1], tags[i]] )
// logits: [S, 50] f32, tags: [S] int (dtype auto-detected int32 vs int64, inline probe),
// transitions: [50, 50] f32. Output: scalar f32.
//
// R4: chunk-of-8 per thread, front-batched tag vector loads -> 8 independent
// gathers (MLP_p1=8). Inline dtype detect per block (ballot). 2-kernel graph.

#define NUM_TAGS 50
#define CHUNK    8
#define TPB      256
#define MAXBLK   4096

__device__ double g_part[MAXBLK];

__global__ void __launch_bounds__(TPB) k_main(
    const float* __restrict__ logits,
    const void*  __restrict__ tags_raw,
    const float* __restrict__ transitions,
    int S)
{
    __shared__ float s_trans[NUM_TAGS * NUM_TAGS];
    __shared__ int   s_is64;

    // --- inline dtype probe: warp 0, 64 entries in parallel ---
    if (threadIdx.x < 32) {
        const long long* t64 = (const long long*)tags_raw;
        bool bad = false;
        #pragma unroll
        for (int k = 0; k < 2; k++) {
            int idx = threadIdx.x + 32 * k;
            if (idx < S) {
                long long v = t64[idx];
                bad |= (v < 0 || v >= NUM_TAGS);
            }
        }
        unsigned m = __ballot_sync(0xFFFFFFFFu, bad);
        if (threadIdx.x == 0) s_is64 = (m == 0) ? 1 : 0;
    }

    // --- stage transitions in smem ---
    for (int i = threadIdx.x; i < NUM_TAGS * NUM_TAGS; i += TPB)
        s_trans[i] = transitions[i];
    __syncthreads();

    const int is64   = s_is64;
    const int chunk0 = (blockIdx.x * TPB + threadIdx.x) * CHUNK;

    float acc = 0.0f;
    int t[CHUNK + 1];

    if (chunk0 + CHUNK < S) {
        // fast path: full chunk, boundary element exists
        if (is64) {
            const long long* tg = (const long long*)tags_raw;
            const longlong2* v  = (const longlong2*)(tg + chunk0);
            #pragma unroll
            for (int k = 0; k < 4; k++) {
                longlong2 p = v[k];
                t[2*k]   = (int)p.x;
                t[2*k+1] = (int)p.y;
            }
            t[CHUNK] = (int)tg[chunk0 + CHUNK];
        } else {
            const int* tg = (const int*)tags_raw;
            int4 a = *(const int4*)(tg + chunk0);
            int4 b = *(const int4*)(tg + chunk0 + 4);
            t[0]=a.x; t[1]=a.y; t[2]=a.z; t[3]=a.w;
            t[4]=b.x; t[5]=b.y; t[6]=b.z; t[7]=b.w;
            t[CHUNK] = tg[chunk0 + CHUNK];
        }

        // 8 independent gathers (front-batched -> MLP=8)
        float e[CHUNK];
        #pragma unroll
        for (int j = 0; j < CHUNK; j++)
            e[j] = __ldg(&logits[(long long)(chunk0 + j) * NUM_TAGS + t[j]]);

        // transitions from smem
        float tr = 0.0f;
        #pragma unroll
        for (int j = 0; j < CHUNK; j++)
            tr += s_trans[t[j] * NUM_TAGS + t[j + 1]];

        #pragma unroll
        for (int j = 0; j < CHUNK; j++)
            acc += e[j];
        acc += tr;
    } else if (chunk0 < S) {
        // tail: scalar path
        if (is64) {
            const long long* tg = (const long long*)tags_raw;
            for (int i = chunk0; i < S; i++) {
                int tt = (int)tg[i];
                acc += logits[(long long)i * NUM_TAGS + tt];
                if (i + 1 < S)
                    acc += s_trans[tt * NUM_TAGS + (int)tg[i + 1]];
            }
        } else {
            const int* tg = (const int*)tags_raw;
            for (int i = chunk0; i < S; i++) {
                int tt = tg[i];
                acc += logits[(long long)i * NUM_TAGS + tt];
                if (i + 1 < S)
                    acc += s_trans[tt * NUM_TAGS + tg[i + 1]];
            }
        }
    }

    // warp reduce
    #pragma unroll
    for (int off = 16; off > 0; off >>= 1)
        acc += __shfl_down_sync(0xFFFFFFFFu, acc, off);

    // block reduce
    __shared__ float s_warp[TPB / 32];
    int lane = threadIdx.x & 31;
    int wid  = threadIdx.x >> 5;
    if (lane == 0) s_warp[wid] = acc;
    __syncthreads();
    if (wid == 0) {
        acc = (lane < (TPB >> 5)) ? s_warp[lane] : 0.0f;
        #pragma unroll
        for (int off = 4; off > 0; off >>= 1)
            acc += __shfl_down_sync(0xFFFFFFFFu, acc, off);
        if (lane == 0)
            g_part[blockIdx.x] = (double)acc;   // plain store, every launch
    }
}

__global__ void __launch_bounds__(1024) k_fin(float* __restrict__ out, int nblocks) {
    __shared__ double s_red[32];
    double acc = 0.0;
    for (int i = threadIdx.x; i < nblocks; i += blockDim.x)
        acc += g_part[i];

    #pragma unroll
    for (int off = 16; off > 0; off >>= 1)
        acc += __shfl_down_sync(0xFFFFFFFFu, acc, off);

    int lane = threadIdx.x & 31;
    int wid  = threadIdx.x >> 5;
    if (lane == 0) s_red[wid] = acc;
    __syncthreads();
    if (wid == 0) {
        acc = (lane < 32) ? s_red[lane] : 0.0;
        #pragma unroll
        for (int off = 16; off > 0; off >>= 1)
            acc += __shfl_down_sync(0xFFFFFFFFu, acc, off);
        if (lane == 0)
            out[0] = (float)(-acc);
    }
}

extern "C" void kernel_launch(void* const* d_in, const int* in_sizes, int n_in,
                              void* d_out, int out_size) {
    const float* logits      = (const float*)d_in[0];
    const void*  tags        = d_in[1];
    const float* transitions = (const float*)d_in[2];
    float*       out         = (float*)d_out;

    const int S = in_sizes[1];  // tags element count = SEQ_LEN

    int blocks = (S + TPB * CHUNK - 1) / (TPB * CHUNK);
    if (blocks > MAXBLK) blocks = MAXBLK;   // S<=8.3M guaranteed by MAXBLK*TPB*CHUNK
    k_main<<<blocks, TPB>>>(logits, tags, transitions, S);
    k_fin<<<1, 1024>>>(out, blocks);
}

// round 5
// speedup vs baseline: 1.0052x; 1.0052x over previous
#include <cuda_runtime.h>
#include <cuda_bf16.h>

// CRF score: -( sum_i logits[i, tags[i]] + sum_{i>0} transitions[tags[i-1], tags[i]] )
// logits: [S, 50] f32, tags: [S] int (dtype auto-detected int32 vs int64, inline probe),
// transitions: [50, 50] f32. Output: scalar f32.
//
// R5: single fused kernel. Chunk-of-8 gathers (MLP=8), inline dtype probe,
// last-block threadfence reduction (index-ordered -> deterministic), counter
// self-resets for graph replay. No second kernel launch.

#define NUM_TAGS 50
#define CHUNK    8
#define TPB      256
#define MAXBLK   4096

__device__ double g_part[MAXBLK];
__device__ unsigned int g_done = 0;   // self-resetting ticket counter

__global__ void __launch_bounds__(TPB) k_fused(
    const float* __restrict__ logits,
    const void*  __restrict__ tags_raw,
    const float* __restrict__ transitions,
    float* __restrict__ out,
    int S)
{
    __shared__ float s_trans[NUM_TAGS * NUM_TAGS];
    __shared__ int   s_is64;
    __shared__ bool  s_last;

    // --- inline dtype probe: warp 0, 64 entries in parallel (L2-hot after blk 0) ---
    if (threadIdx.x < 32) {
        const long long* t64 = (const long long*)tags_raw;
        bool bad = false;
        #pragma unroll
        for (int k = 0; k < 2; k++) {
            int idx = threadIdx.x + 32 * k;
            if (idx < S) {
                long long v = t64[idx];
                bad |= (v < 0 || v >= NUM_TAGS);
            }
        }
        unsigned m = __ballot_sync(0xFFFFFFFFu, bad);
        if (threadIdx.x == 0) s_is64 = (m == 0) ? 1 : 0;
    }

    // --- stage transitions in smem ---
    for (int i = threadIdx.x; i < NUM_TAGS * NUM_TAGS; i += TPB)
        s_trans[i] = transitions[i];
    __syncthreads();

    const int is64   = s_is64;
    const int chunk0 = (blockIdx.x * TPB + threadIdx.x) * CHUNK;

    float acc = 0.0f;
    int t[CHUNK + 1];

    if (chunk0 + CHUNK < S) {
        // fast path: full chunk + boundary element
        if (is64) {
            const long long* tg = (const long long*)tags_raw;
            const longlong2* v  = (const longlong2*)(tg + chunk0);
            #pragma unroll
            for (int k = 0; k < 4; k++) {
                longlong2 p = v[k];
                t[2*k]   = (int)p.x;
                t[2*k+1] = (int)p.y;
            }
            t[CHUNK] = (int)tg[chunk0 + CHUNK];
        } else {
            const int* tg = (const int*)tags_raw;
            int4 a = *(const int4*)(tg + chunk0);
            int4 b = *(const int4*)(tg + chunk0 + 4);
            t[0]=a.x; t[1]=a.y; t[2]=a.z; t[3]=a.w;
            t[4]=b.x; t[5]=b.y; t[6]=b.z; t[7]=b.w;
            t[CHUNK] = tg[chunk0 + CHUNK];
        }

        // 8 independent streaming gathers (front-batched -> MLP=8, no reuse -> evict-first)
        float e[CHUNK];
        #pragma unroll
        for (int j = 0; j < CHUNK; j++)
            e[j] = __ldcs(&logits[(long long)(chunk0 + j) * NUM_TAGS + t[j]]);

        float tr = 0.0f;
        #pragma unroll
        for (int j = 0; j < CHUNK; j++)
            tr += s_trans[t[j] * NUM_TAGS + t[j + 1]];

        #pragma unroll
        for (int j = 0; j < CHUNK; j++)
            acc += e[j];
        acc += tr;
    } else if (chunk0 < S) {
        // tail: scalar path
        if (is64) {
            const long long* tg = (const long long*)tags_raw;
            for (int i = chunk0; i < S; i++) {
                int tt = (int)tg[i];
                acc += logits[(long long)i * NUM_TAGS + tt];
                if (i + 1 < S)
                    acc += s_trans[tt * NUM_TAGS + (int)tg[i + 1]];
            }
        } else {
            const int* tg = (const int*)tags_raw;
            for (int i = chunk0; i < S; i++) {
                int tt = tg[i];
                acc += logits[(long long)i * NUM_TAGS + tt];
                if (i + 1 < S)
                    acc += s_trans[tt * NUM_TAGS + tg[i + 1]];
            }
        }
    }

    // --- block reduce ---
    #pragma unroll
    for (int off = 16; off > 0; off >>= 1)
        acc += __shfl_down_sync(0xFFFFFFFFu, acc, off);

    __shared__ float s_warp[TPB / 32];
    int lane = threadIdx.x & 31;
    int wid  = threadIdx.x >> 5;
    if (lane == 0) s_warp[wid] = acc;
    __syncthreads();
    if (wid == 0) {
        acc = (lane < (TPB >> 5)) ? s_warp[lane] : 0.0f;
        #pragma unroll
        for (int off = 4; off > 0; off >>= 1)
            acc += __shfl_down_sync(0xFFFFFFFFu, acc, off);
        if (lane == 0)
            g_part[blockIdx.x] = (double)acc;
    }

    // --- last-block final reduction (threadfence pattern) ---
    if (threadIdx.x == 0) {
        __threadfence();
        unsigned int ticket = atomicAdd(&g_done, 1u);
        s_last = (ticket == gridDim.x - 1);
    }
    __syncthreads();

    if (s_last) {
        __shared__ double s_red[TPB / 32];
        double d = 0.0;
        // index-ordered strided read -> deterministic tree regardless of block order
        for (int i = threadIdx.x; i < (int)gridDim.x; i += TPB)
            d += g_part[i];

        #pragma unroll
        for (int off = 16; off > 0; off >>= 1)
            d += __shfl_down_sync(0xFFFFFFFFu, d, off);
        if (lane == 0) s_red[wid] = d;
        __syncthreads();
        if (wid == 0) {
            d = (lane < (TPB >> 5)) ? s_red[lane] : 0.0;
            #pragma unroll
            for (int off = 4; off > 0; off >>= 1)
                d += __shfl_down_sync(0xFFFFFFFFu, d, off);
            if (lane == 0) {
                out[0] = (float)(-d);
                g_done = 0;               // reset for next graph replay
            }
        }
    }
}

extern "C" void kernel_launch(void* const* d_in, const int* in_sizes, int n_in,
                              void* d_out, int out_size) {
    const float* logits      = (const float*)d_in[0];
    const void*  tags        = d_in[1];
    const float* transitions = (const float*)d_in[2];
    float*       out         = (float*)d_out;

    const int S = in_sizes[1];  // tags element count = SEQ_LEN

    int blocks = (S + TPB * CHUNK - 1) / (TPB * CHUNK);
    if (blocks > MAXBLK) blocks = MAXBLK;
    k_fused<<<blocks, TPB>>>(logits, tags, transitions, out, S);
}

// round 6
// speedup vs baseline: 1.0085x; 1.0033x over previous
#include <cuda_runtime.h>
#include <cuda_bf16.h>

// CRF score: -( sum_i logits[i, tags[i]] + sum_{i>0} transitions[tags[i-1], tags[i]] )
// logits: [S, 50] f32, tags: [S] int (dtype auto-detected int32 vs int64, inline probe),
// transitions: [50, 50] f32. Output: scalar f32.
//
// R6: CHUNK=16 — 16 independent front-batched gathers per thread. Little's law:
// ~32 warps/SM x 16 in-flight = 512 outstanding loads/SM -> saturate DRAM
// random-sector ceiling (R5 measured exactly the 184-outstanding limit, 4.4TB/s).

#define NUM_TAGS 50
#define CHUNK    16
#define TPB      256
#define MAXBLK   4096

__device__ double g_part[MAXBLK];
__device__ unsigned int g_done = 0;   // self-resetting ticket counter

__global__ void __launch_bounds__(TPB) k_fused(
    const float* __restrict__ logits,
    const void*  __restrict__ tags_raw,
    const float* __restrict__ transitions,
    float* __restrict__ out,
    int S)
{
    __shared__ float s_trans[NUM_TAGS * NUM_TAGS];
    __shared__ int   s_is64;
    __shared__ bool  s_last;

    // --- inline dtype probe: warp 0, 64 entries in parallel (L2-hot after blk 0) ---
    if (threadIdx.x < 32) {
        const long long* t64 = (const long long*)tags_raw;
        bool bad = false;
        #pragma unroll
        for (int k = 0; k < 2; k++) {
            int idx = threadIdx.x + 32 * k;
            if (idx < S) {
                long long v = t64[idx];
                bad |= (v < 0 || v >= NUM_TAGS);
            }
        }
        unsigned m = __ballot_sync(0xFFFFFFFFu, bad);
        if (threadIdx.x == 0) s_is64 = (m == 0) ? 1 : 0;
    }

    // --- stage transitions in smem ---
    for (int i = threadIdx.x; i < NUM_TAGS * NUM_TAGS; i += TPB)
        s_trans[i] = transitions[i];
    __syncthreads();

    const int is64   = s_is64;
    const int chunk0 = (blockIdx.x * TPB + threadIdx.x) * CHUNK;

    float acc = 0.0f;
    int t[CHUNK + 1];

    if (chunk0 + CHUNK < S) {
        // fast path: full chunk + boundary element
        if (is64) {
            const long long* tg = (const long long*)tags_raw;
            const longlong2* v  = (const longlong2*)(tg + chunk0);
            #pragma unroll
            for (int k = 0; k < CHUNK / 2; k++) {
                longlong2 p = v[k];
                t[2*k]   = (int)p.x;
                t[2*k+1] = (int)p.y;
            }
            t[CHUNK] = (int)tg[chunk0 + CHUNK];
        } else {
            const int* tg = (const int*)tags_raw;
            #pragma unroll
            for (int k = 0; k < CHUNK / 4; k++) {
                int4 a = *(const int4*)(tg + chunk0 + 4 * k);
                t[4*k]   = a.x;
                t[4*k+1] = a.y;
                t[4*k+2] = a.z;
                t[4*k+3] = a.w;
            }
            t[CHUNK] = tg[chunk0 + CHUNK];
        }

        // 16 independent streaming gathers (front-batched -> MLP=16)
        float e[CHUNK];
        #pragma unroll
        for (int j = 0; j < CHUNK; j++)
            e[j] = __ldcs(&logits[(long long)(chunk0 + j) * NUM_TAGS + t[j]]);

        // transitions from smem while gathers are in flight
        float tr = 0.0f;
        #pragma unroll
        for (int j = 0; j < CHUNK; j++)
            tr += s_trans[t[j] * NUM_TAGS + t[j + 1]];

        #pragma unroll
        for (int j = 0; j < CHUNK; j++)
            acc += e[j];
        acc += tr;
    } else if (chunk0 < S) {
        // tail: scalar path
        if (is64) {
            const long long* tg = (const long long*)tags_raw;
            for (int i = chunk0; i < S; i++) {
                int tt = (int)tg[i];
                acc += logits[(long long)i * NUM_TAGS + tt];
                if (i + 1 < S)
                    acc += s_trans[tt * NUM_TAGS + (int)tg[i + 1]];
            }
        } else {
            const int* tg = (const int*)tags_raw;
            for (int i = chunk0; i < S; i++) {
                int tt = tg[i];
                acc += logits[(long long)i * NUM_TAGS + tt];
                if (i + 1 < S)
                    acc += s_trans[tt * NUM_TAGS + tg[i + 1]];
            }
        }
    }

    // --- block reduce ---
    #pragma unroll
    for (int off = 16; off > 0; off >>= 1)
        acc += __shfl_down_sync(0xFFFFFFFFu, acc, off);

    __shared__ float s_warp[TPB / 32];
    int lane = threadIdx.x & 31;
    int wid  = threadIdx.x >> 5;
    if (lane == 0) s_warp[wid] = acc;
    __syncthreads();
    if (wid == 0) {
        acc = (lane < (TPB >> 5)) ? s_warp[lane] : 0.0f;
        #pragma unroll
        for (int off = 4; off > 0; off >>= 1)
            acc += __shfl_down_sync(0xFFFFFFFFu, acc, off);
        if (lane == 0)
            g_part[blockIdx.x] = (double)acc;
    }

    // --- last-block final reduction (threadfence pattern, index-ordered = deterministic) ---
    if (threadIdx.x == 0) {
        __threadfence();
        unsigned int ticket = atomicAdd(&g_done, 1u);
        s_last = (ticket == gridDim.x - 1);
    }
    __syncthreads();

    if (s_last) {
        __shared__ double s_red[TPB / 32];
        double d = 0.0;
        for (int i = threadIdx.x; i < (int)gridDim.x; i += TPB)
            d += g_part[i];

        #pragma unroll
        for (int off = 16; off > 0; off >>= 1)
            d += __shfl_down_sync(0xFFFFFFFFu, d, off);
        if (lane == 0) s_red[wid] = d;
        __syncthreads();
        if (wid == 0) {
            d = (lane < (TPB >> 5)) ? s_red[lane] : 0.0;
            #pragma unroll
            for (int off = 4; off > 0; off >>= 1)
                d += __shfl_down_sync(0xFFFFFFFFu, d, off);
            if (lane == 0) {
                out[0] = (float)(-d);
                g_done = 0;               // reset for next graph replay
            }
        }
    }
}

extern "C" void kernel_launch(void* const* d_in, const int* in_sizes, int n_in,
                              void* d_out, int out_size) {
    const float* logits      = (const float*)d_in[0];
    const void*  tags        = d_in[1];
    const float* transitions = (const float*)d_in[2];
    float*       out         = (float*)d_out;

    const int S = in_sizes[1];  // tags element count = SEQ_LEN

    int blocks = (S + TPB * CHUNK - 1) / (TPB * CHUNK);
    if (blocks > MAXBLK) blocks = MAXBLK;
    k_fused<<<blocks, TPB>>>(logits, tags, transitions, out, S);
}

// round 7
// speedup vs baseline: 1.0423x; 1.0336x over previous
#include <cuda_runtime.h>
#include <cuda_bf16.h>

// CRF score: -( sum_i logits[i, tags[i]] + sum_{i>0} transitions[tags[i-1], tags[i]] )
// logits: [S, 50] f32, tags: [S] int (dtype auto-detected int32 vs int64, inline probe),
// transitions: [50, 50] f32. Output: scalar f32.
//
// R7: WARP-INTERLEAVED layout. A warp owns 512 consecutive elements; element for
// (lane, j) = base + lane + 32*j. Each gather instruction's 32 addresses span one
// contiguous 6400B window (50 lines) -> L1tex merges to ~24 line requests (25%
// DRAM traffic cut vs per-thread chunking) + sequential DRAM row locality.
// Transition partner tag via shfl_down (lane+1), lane-31 fixup from t[j+1].

#define NUM_TAGS 50
#define CHUNK    16                    // elements per lane -> 512 per warp
#define WELEM    (32 * CHUNK)          // 512
#define TPB      256
#define WPB      (TPB / 32)            // 8 warps/block
#define MAXBLK   4096
#define FULLM    0xFFFFFFFFu

__device__ double g_part[MAXBLK];
__device__ unsigned int g_done = 0;    // self-resetting ticket counter

__global__ void __launch_bounds__(TPB) k_fused(
    const float* __restrict__ logits,
    const void*  __restrict__ tags_raw,
    const float* __restrict__ transitions,
    float* __restrict__ out,
    int S)
{
    __shared__ float s_trans[NUM_TAGS * NUM_TAGS];
    __shared__ int   s_is64;
    __shared__ bool  s_last;

    // --- inline dtype probe: warp 0, 64 entries in parallel (L2-hot after blk 0) ---
    if (threadIdx.x < 32) {
        const long long* t64 = (const long long*)tags_raw;
        bool bad = false;
        #pragma unroll
        for (int k = 0; k < 2; k++) {
            int idx = threadIdx.x + 32 * k;
            if (idx < S) {
                long long v = t64[idx];
                bad |= (v < 0 || v >= NUM_TAGS);
            }
        }
        unsigned m = __ballot_sync(FULLM, bad);
        if (threadIdx.x == 0) s_is64 = (m == 0) ? 1 : 0;
    }

    // --- stage transitions in smem ---
    for (int i = threadIdx.x; i < NUM_TAGS * NUM_TAGS; i += TPB)
        s_trans[i] = transitions[i];
    __syncthreads();

    const int is64 = s_is64;
    const int lane = threadIdx.x & 31;
    const int warp = (blockIdx.x * WPB) + (threadIdx.x >> 5);
    const int base = warp * WELEM;

    float acc = 0.0f;

    if (base + WELEM < S) {
        // ---- fast path: full warp tile, boundary tags[base+512] exists ----
        int t[CHUNK];
        if (is64) {
            const long long* tg = (const long long*)tags_raw;
            #pragma unroll
            for (int j = 0; j < CHUNK; j++)
                t[j] = (int)tg[base + lane + 32 * j];      // coalesced per j
        } else {
            const int* tg = (const int*)tags_raw;
            #pragma unroll
            for (int j = 0; j < CHUNK; j++)
                t[j] = tg[base + lane + 32 * j];           // 1 line per instr
        }
        // boundary tag for lane31, j=CHUNK-1: element base+512
        int t_follow = 0;
        if (lane == 31)
            t_follow = is64 ? (int)((const long long*)tags_raw)[base + WELEM]
                            : ((const int*)tags_raw)[base + WELEM];

        // 16 independent gathers, each instr spans one 6400B window
        float e[CHUNK];
        #pragma unroll
        for (int j = 0; j < CHUNK; j++) {
            int i = base + lane + 32 * j;
            e[j] = __ldg(&logits[(long long)i * NUM_TAGS + t[j]]);
        }

        // transitions: partner tag of element i is element i+1 = (lane+1, j),
        // or (0, j+1) when lane==31, or t_follow at the very end.
        float tr = 0.0f;
        #pragma unroll
        for (int j = 0; j < CHUNK; j++) {
            int down = __shfl_down_sync(FULLM, t[j], 1);   // lane31 gets garbage
            int wrap;
            if (j < CHUNK - 1)
                wrap = __shfl_sync(FULLM, t[j + 1], 0);    // lane0's next-j tag
            else
                wrap = t_follow;                            // valid on lane31
            int tn = (lane == 31) ? wrap : down;
            tr += s_trans[t[j] * NUM_TAGS + tn];
        }

        #pragma unroll
        for (int j = 0; j < CHUNK; j++)
            acc += e[j];
        acc += tr;
    } else if (base < S) {
        // ---- tail: scalar per-lane loop ----
        if (is64) {
            const long long* tg = (const long long*)tags_raw;
            for (int i = base + lane; i < S; i += 32) {
                int tt = (int)tg[i];
                acc += logits[(long long)i * NUM_TAGS + tt];
                if (i + 1 < S)
                    acc += s_trans[tt * NUM_TAGS + (int)tg[i + 1]];
            }
        } else {
            const int* tg = (const int*)tags_raw;
            for (int i = base + lane; i < S; i += 32) {
                int tt = tg[i];
                acc += logits[(long long)i * NUM_TAGS + tt];
                if (i + 1 < S)
                    acc += s_trans[tt * NUM_TAGS + tg[i + 1]];
            }
        }
    }

    // --- block reduce ---
    #pragma unroll
    for (int off = 16; off > 0; off >>= 1)
        acc += __shfl_down_sync(FULLM, acc, off);

    __shared__ float s_warp[WPB];
    int wid = threadIdx.x >> 5;
    if (lane == 0) s_warp[wid] = acc;
    __syncthreads();
    if (wid == 0) {
        acc = (lane < WPB) ? s_warp[lane] : 0.0f;
        #pragma unroll
        for (int off = 4; off > 0; off >>= 1)
            acc += __shfl_down_sync(FULLM, acc, off);
        if (lane == 0)
            g_part[blockIdx.x] = (double)acc;
    }

    // --- last-block final reduction (index-ordered = deterministic) ---
    if (threadIdx.x == 0) {
        __threadfence();
        unsigned int ticket = atomicAdd(&g_done, 1u);
        s_last = (ticket == gridDim.x - 1);
    }
    __syncthreads();

    if (s_last) {
        __shared__ double s_red[WPB];
        double d = 0.0;
        for (int i = threadIdx.x; i < (int)gridDim.x; i += TPB)
            d += g_part[i];

        #pragma unroll
        for (int off = 16; off > 0; off >>= 1)
            d += __shfl_down_sync(FULLM, d, off);
        if (lane == 0) s_red[wid] = d;
        __syncthreads();
        if (wid == 0) {
            d = (lane < WPB) ? s_red[lane] : 0.0;
            #pragma unroll
            for (int off = 4; off > 0; off >>= 1)
                d += __shfl_down_sync(FULLM, d, off);
            if (lane == 0) {
                out[0] = (float)(-d);
                g_done = 0;            // reset for next graph replay
            }
        }
    }
}

extern "C" void kernel_launch(void* const* d_in, const int* in_sizes, int n_in,
                              void* d_out, int out_size) {
    const float* logits      = (const float*)d_in[0];
    const void*  tags        = d_in[1];
    const float* transitions = (const float*)d_in[2];
    float*       out         = (float*)d_out;

    const int S = in_sizes[1];  // tags element count = SEQ_LEN

    int warps  = (S + WELEM - 1) / WELEM;
    int blocks = (warps + WPB - 1) / WPB;
    if (blocks > MAXBLK) blocks = MAXBLK;
    k_fused<<<blocks, TPB>>>(logits, tags, transitions, out, S);
}